// round 3
// baseline (speedup 1.0000x reference)
#include <cuda_runtime.h>
#include <cstdint>

// ================= problem dims =================
static constexpr int M_TOTAL = 16384;   // B*S = 4*4096
static constexpr int N_TOTAL = 12288;   // 3*E
static constexpr int K_TOTAL = 4096;    // E
static constexpr int TILE_M  = 128;
static constexpr int TILE_N  = 256;
static constexpr int TILE_K  = 32;      // 32 tf32 = 128B rows (swizzle atom)
static constexpr int STAGES  = 4;
static constexpr int KCHUNKS = K_TOTAL / TILE_K;  // 128
static constexpr int MT = M_TOTAL / TILE_M;       // 128
static constexpr int NT = N_TOTAL / TILE_N;       // 48
static constexpr int GROUP_M = 12;

static constexpr int A_TILE_BYTES = TILE_M * TILE_K * 4;   // 16384
static constexpr int B_TILE_BYTES = TILE_N * TILE_K * 4;   // 32768
static constexpr int STAGE_BYTES  = A_TILE_BYTES + B_TILE_BYTES; // 49152
static constexpr int SMEM_BYTES   = STAGES * STAGE_BYTES;        // 196608

// tf32-rounded (RN) copies of the inputs. __device__ scratch — no dynamic alloc.
__device__ float g_Xtf[(size_t)M_TOTAL * K_TOTAL];
__device__ float g_Wtf[(size_t)N_TOTAL * K_TOTAL];

// ================= helpers =================
__device__ __forceinline__ uint32_t smem_u32(const void* p) {
    uint32_t a;
    asm("{ .reg .u64 t; cvta.to.shared.u64 t, %1; cvt.u32.u64 %0, t; }"
        : "=r"(a) : "l"(p));
    return a;
}

__device__ __forceinline__ void cp_async16(uint32_t dst, const void* src) {
    asm volatile("cp.async.cg.shared.global [%0], [%1], 16;" :: "r"(dst), "l"(src));
}
__device__ __forceinline__ void cp_commit() {
    asm volatile("cp.async.commit_group;" ::: "memory");
}
template <int N>
__device__ __forceinline__ void cp_wait() {
    asm volatile("cp.async.wait_group %0;" :: "n"(N) : "memory");
}

// 128B-block swizzle: XOR 16B-unit low bits with row bits
#define SWZ(o) ((o) ^ (((o) >> 3) & 0x70))

// classic warp MMA (sm_80+, legal on plain sm_103 target)
__device__ __forceinline__ void mma_sync_tf32(float* c, const uint32_t* a,
                                              const uint32_t* b) {
    asm volatile(
        "mma.sync.aligned.m16n8k8.row.col.f32.tf32.tf32.f32 "
        "{%0,%1,%2,%3}, {%4,%5,%6,%7}, {%8,%9}, {%0,%1,%2,%3};"
        : "+f"(c[0]), "+f"(c[1]), "+f"(c[2]), "+f"(c[3])
        : "r"(a[0]), "r"(a[1]), "r"(a[2]), "r"(a[3]),
          "r"(b[0]), "r"(b[1]));
}

// ================= tf32 RN conversion pre-pass =================
__device__ __forceinline__ float to_tf32(float x) {
    uint32_t u;
    asm("cvt.rna.tf32.f32 %0, %1;" : "=r"(u) : "f"(x));
    return __uint_as_float(u);
}

__global__ void __launch_bounds__(256)
cvt_tf32_kernel(const float* __restrict__ in, float* __restrict__ outp, int n4) {
    const float4* s = (const float4*)in;
    float4* d = (float4*)outp;
    int i = blockIdx.x * blockDim.x + threadIdx.x;
    int stride = gridDim.x * blockDim.x;
    for (; i < n4; i += stride) {
        float4 v = s[i];
        v.x = to_tf32(v.x); v.y = to_tf32(v.y);
        v.z = to_tf32(v.z); v.w = to_tf32(v.w);
        d[i] = v;
    }
}

// ================= GEMM kernel (cp.async multistage + mma.sync tf32) =========
__global__ void __launch_bounds__(256, 1)
qkv_gemm_kernel(float* __restrict__ out) {
    extern __shared__ __align__(1024) char smem[];
    const uint32_t sb = smem_u32(smem);
    const int tid = threadIdx.x;
    const int wid = tid >> 5;
    const int lid = tid & 31;

    // ---- tile mapping (grouped raster for L2 reuse) ----
    int bid = blockIdx.x;
    const int TPG = GROUP_M * NT;
    int g   = bid / TPG;
    int rem = bid % TPG;
    int m0g = g * GROUP_M;
    int rows = (MT - m0g) < GROUP_M ? (MT - m0g) : GROUP_M;
    int mtile = m0g + rem % rows;
    int ntile = rem / rows;
    const int m0 = mtile * TILE_M;
    const int n0 = ntile * TILE_N;

    // ---- per-thread load segments: 12 x 16B per stage (3072 total) ----
    const float* segg[12];
    uint32_t segso[12];
#pragma unroll
    for (int i = 0; i < 12; ++i) {
        int s = tid + 256 * i;
        if (s < 1024) {              // A: 128 rows x 8 segs of 16B
            int r = s >> 3, j = s & 7;
            segg[i]  = g_Xtf + (size_t)(m0 + r) * K_TOTAL + j * 4;
            segso[i] = SWZ((uint32_t)(r * 128 + j * 16));
        } else {                     // B: 256 rows x 8 segs of 16B
            int t = s - 1024;
            int r = t >> 3, j = t & 7;
            segg[i]  = g_Wtf + (size_t)(n0 + r) * K_TOTAL + j * 4;
            segso[i] = (uint32_t)A_TILE_BYTES + SWZ((uint32_t)(r * 128 + j * 16));
        }
    }

    auto produce = [&](int c) {
        uint32_t dstb = sb + (uint32_t)(c & (STAGES - 1)) * STAGE_BYTES;
        const int k0 = c * TILE_K;
#pragma unroll
        for (int i = 0; i < 12; ++i)
            cp_async16(dstb + segso[i], segg[i] + k0);
        cp_commit();
    };

    // ---- prologue: stages 0..S-2 in flight ----
#pragma unroll
    for (int c = 0; c < STAGES - 1; ++c) produce(c);
    cp_wait<STAGES - 2>();        // stage 0 resident (this thread's copies)
    __syncthreads();              // ... and everyone's

    // ---- accumulators: 8 warps (2x4), warp tile 64x64, mma m16n8k8 ----
    float acc[4][8][4];
#pragma unroll
    for (int mt = 0; mt < 4; ++mt)
#pragma unroll
        for (int nt = 0; nt < 8; ++nt)
#pragma unroll
            for (int j = 0; j < 4; ++j) acc[mt][nt][j] = 0.0f;

    const int wm = wid & 1, wn = wid >> 1;
    const int mbase = wm * 64, nbase = wn * 64;
    const int qr = lid >> 2, qc = lid & 3;

#pragma unroll 1
    for (int c = 0; c < KCHUNKS; ++c) {
        // issue loads for stage c+S-1 into slot (c-1)%S (freed by barrier below)
        if (c + STAGES - 1 < KCHUNKS) produce(c + STAGES - 1);

        const char* base = smem + (size_t)(c & (STAGES - 1)) * STAGE_BYTES;
#pragma unroll
        for (int kk = 0; kk < 4; ++kk) {
            const int kb = kk * 32 + qc * 4;   // byte offset of k for a0/b0
            uint32_t a[4][4], b[8][2];
#pragma unroll
            for (int mt = 0; mt < 4; ++mt) {
                int r0 = mbase + mt * 16 + qr;
                a[mt][0] = *(const uint32_t*)(base + SWZ((uint32_t)(r0 * 128 + kb)));
                a[mt][1] = *(const uint32_t*)(base + SWZ((uint32_t)((r0 + 8) * 128 + kb)));
                a[mt][2] = *(const uint32_t*)(base + SWZ((uint32_t)(r0 * 128 + kb + 16)));
                a[mt][3] = *(const uint32_t*)(base + SWZ((uint32_t)((r0 + 8) * 128 + kb + 16)));
            }
#pragma unroll
            for (int nt = 0; nt < 8; ++nt) {
                int n = nbase + nt * 8 + qr;
                b[nt][0] = *(const uint32_t*)(base + A_TILE_BYTES + SWZ((uint32_t)(n * 128 + kb)));
                b[nt][1] = *(const uint32_t*)(base + A_TILE_BYTES + SWZ((uint32_t)(n * 128 + kb + 16)));
            }
#pragma unroll
            for (int mt = 0; mt < 4; ++mt)
#pragma unroll
                for (int nt = 0; nt < 8; ++nt)
                    mma_sync_tf32(acc[mt][nt], a[mt], b[nt]);
        }

        cp_wait<STAGES - 2>();   // stage c+1's copies (this thread) complete
        __syncthreads();         // visible to all; slot (c)%S free for iter c+1
    }

    // ---- epilogue: regs -> GMEM with q/k/v region remap ----
    // out column n -> region r = n>>12, elem e = n&4095; region stride M*4096
    {
        const int rgn = n0 >> 12;
        float* obase = out + (size_t)rgn * ((size_t)M_TOTAL * 4096)
                           + (size_t)m0 * 4096 + (size_t)(n0 & 4095);
#pragma unroll
        for (int mt = 0; mt < 4; ++mt) {
            int m = mbase + mt * 16 + qr;
#pragma unroll
            for (int nt = 0; nt < 8; ++nt) {
                int ncol = nbase + nt * 8 + 2 * qc;
                *(float2*)(obase + (size_t)m * 4096 + ncol) =
                    make_float2(acc[mt][nt][0], acc[mt][nt][1]);
                *(float2*)(obase + (size_t)(m + 8) * 4096 + ncol) =
                    make_float2(acc[mt][nt][2], acc[mt][nt][3]);
            }
        }
    }
}

// ================= launch =================
extern "C" void kernel_launch(void* const* d_in, const int* in_sizes, int n_in,
                              void* d_out, int out_size) {
    const float* X = (const float*)d_in[0];   // hidden_states [4,4096,4096]
    const float* W = (const float*)d_in[1];   // qkv_proj [12288,4096]
    float* out = (float*)d_out;               // q|k|v, 3 x [16384,4096]
    (void)in_sizes; (void)n_in; (void)out_size;

    cudaFuncSetAttribute(qkv_gemm_kernel,
                         cudaFuncAttributeMaxDynamicSharedMemorySize, SMEM_BYTES);

    float* Xtf = nullptr;
    float* Wtf = nullptr;
    cudaGetSymbolAddress((void**)&Xtf, g_Xtf);
    cudaGetSymbolAddress((void**)&Wtf, g_Wtf);

    cvt_tf32_kernel<<<1184, 256>>>(X, Xtf, (M_TOTAL * (K_TOTAL / 4)));
    cvt_tf32_kernel<<<1184, 256>>>(W, Wtf, (N_TOTAL * (K_TOTAL / 4)));
    qkv_gemm_kernel<<<MT * NT, 256, SMEM_BYTES>>>(out);
}

// round 4
// speedup vs baseline: 2.0636x; 2.0636x over previous
#include <cuda_runtime.h>
#include <cuda_fp16.h>
#include <cstdint>

// ================= problem dims =================
static constexpr int M_TOTAL = 16384;   // B*S = 4*4096
static constexpr int N_TOTAL = 12288;   // 3*E
static constexpr int K_TOTAL = 4096;    // E
static constexpr int TILE_M  = 128;
static constexpr int TILE_N  = 256;
static constexpr int TILE_K  = 64;      // 64 halves = 128B rows (SW128 atom)
static constexpr int STAGES  = 4;
static constexpr int KCHUNKS = K_TOTAL / TILE_K;  // 64
static constexpr int MT = M_TOTAL / TILE_M;       // 128
static constexpr int NT = N_TOTAL / TILE_N;       // 48
static constexpr int GROUP_M = 12;

static constexpr int A_TILE_BYTES = TILE_M * TILE_K * 2;   // 16384
static constexpr int B_TILE_BYTES = TILE_N * TILE_K * 2;   // 32768
static constexpr int STAGE_BYTES  = A_TILE_BYTES + B_TILE_BYTES; // 49152
static constexpr int SMEM_BYTES   = STAGES * STAGE_BYTES;        // 196608

// fp16 copies of the inputs (RN). fp16 mantissa == tf32 mantissa (10 bits),
// so precision matches the tf32 run (measured 2.9e-4), at 2x HMMA throughput.
__device__ __half g_Xh[(size_t)M_TOTAL * K_TOTAL];
__device__ __half g_Wh[(size_t)N_TOTAL * K_TOTAL];

// ================= helpers =================
__device__ __forceinline__ uint32_t smem_u32(const void* p) {
    uint32_t a;
    asm("{ .reg .u64 t; cvta.to.shared.u64 t, %1; cvt.u32.u64 %0, t; }"
        : "=r"(a) : "l"(p));
    return a;
}

__device__ __forceinline__ void cp_async16(uint32_t dst, const void* src) {
    asm volatile("cp.async.cg.shared.global [%0], [%1], 16;" :: "r"(dst), "l"(src));
}
__device__ __forceinline__ void cp_commit() {
    asm volatile("cp.async.commit_group;" ::: "memory");
}
template <int N>
__device__ __forceinline__ void cp_wait() {
    asm volatile("cp.async.wait_group %0;" :: "n"(N) : "memory");
}

// 128B-block swizzle: XOR 16B-unit index with low 3 row bits
#define SWZ(o) ((o) ^ (((o) >> 3) & 0x70))

// fp16 MMA, fp32 accumulate (sm_80+, legal on plain sm_103 target)
__device__ __forceinline__ void mma_f16(float* c, const uint32_t* a,
                                        const uint32_t* b) {
    asm volatile(
        "mma.sync.aligned.m16n8k16.row.col.f32.f16.f16.f32 "
        "{%0,%1,%2,%3}, {%4,%5,%6,%7}, {%8,%9}, {%0,%1,%2,%3};"
        : "+f"(c[0]), "+f"(c[1]), "+f"(c[2]), "+f"(c[3])
        : "r"(a[0]), "r"(a[1]), "r"(a[2]), "r"(a[3]),
          "r"(b[0]), "r"(b[1]));
}

// ================= fp32 -> fp16 RN pre-pass =================
__global__ void __launch_bounds__(256)
cvt_f16_kernel(const float* __restrict__ in, __half* __restrict__ outp, int n4) {
    const float4* s = (const float4*)in;
    int i = blockIdx.x * blockDim.x + threadIdx.x;
    int stride = gridDim.x * blockDim.x;
    for (; i < n4; i += stride) {
        float4 v = s[i];
        __half2 h0 = __floats2half2_rn(v.x, v.y);
        __half2 h1 = __floats2half2_rn(v.z, v.w);
        uint2 pack = make_uint2(*(uint32_t*)&h0, *(uint32_t*)&h1);
        *(uint2*)(outp + (size_t)i * 4) = pack;
    }
}

// ================= GEMM kernel (cp.async multistage + mma.sync fp16) =========
__global__ void __launch_bounds__(256, 1)
qkv_gemm_kernel(float* __restrict__ out) {
    extern __shared__ __align__(1024) char smem[];
    const uint32_t sb = smem_u32(smem);
    const int tid = threadIdx.x;
    const int wid = tid >> 5;
    const int lid = tid & 31;

    // ---- tile mapping (grouped raster for L2 reuse) ----
    int bid = blockIdx.x;
    const int TPG = GROUP_M * NT;
    int g   = bid / TPG;
    int rem = bid % TPG;
    int m0g = g * GROUP_M;
    int rows = (MT - m0g) < GROUP_M ? (MT - m0g) : GROUP_M;
    int mtile = m0g + rem % rows;
    int ntile = rem / rows;
    const int m0 = mtile * TILE_M;
    const int n0 = ntile * TILE_N;

    // ---- producer bases (segment math collapses to base + i*stride) ----
    // thread covers A rows r0+32i (i<4) and B rows r0+32i (i<8), 16B seg j.
    const int r0 = tid >> 3;          // 0..31
    const int j  = tid & 7;           // 16B segment within 128B row
    const __half* gA0 = g_Xh + (size_t)(m0 + r0) * K_TOTAL + j * 8;
    const __half* gB0 = g_Wh + (size_t)(n0 + r0) * K_TOTAL + j * 8;
    const uint32_t swzA = SWZ((uint32_t)(r0 * 128 + j * 16));
    const uint32_t swzB = (uint32_t)A_TILE_BYTES + SWZ((uint32_t)(r0 * 128 + j * 16));

    auto produce = [&](int c) {
        uint32_t dstb = sb + (uint32_t)(c & (STAGES - 1)) * STAGE_BYTES;
        const __half* ga = gA0 + (size_t)c * TILE_K;
        const __half* gb = gB0 + (size_t)c * TILE_K;
#pragma unroll
        for (int i = 0; i < 4; ++i)
            cp_async16(dstb + swzA + i * 4096u, ga + (size_t)i * 32 * K_TOTAL);
#pragma unroll
        for (int i = 0; i < 8; ++i)
            cp_async16(dstb + swzB + i * 4096u, gb + (size_t)i * 32 * K_TOTAL);
        cp_commit();
    };

    // ---- prologue: stages 0..S-2 in flight ----
#pragma unroll
    for (int c = 0; c < STAGES - 1; ++c) produce(c);
    cp_wait<STAGES - 2>();
    __syncthreads();

    // ---- accumulators: 8 warps (2x4), warp tile 64x64, mma m16n8k16 ----
    float acc[4][8][4];
#pragma unroll
    for (int mt = 0; mt < 4; ++mt)
#pragma unroll
        for (int nt = 0; nt < 8; ++nt)
#pragma unroll
            for (int jj = 0; jj < 4; ++jj) acc[mt][nt][jj] = 0.0f;

    const int wm = wid & 1, wn = wid >> 1;
    const int mbase = wm * 64, nbase = wn * 64;
    const int qr = lid >> 2, qc = lid & 3;

#pragma unroll 1
    for (int c = 0; c < KCHUNKS; ++c) {
        if (c + STAGES - 1 < KCHUNKS) produce(c + STAGES - 1);

        const char* base = smem + (size_t)(c & (STAGES - 1)) * STAGE_BYTES;
#pragma unroll
        for (int kk = 0; kk < 4; ++kk) {          // 4 x k16 within 64-K chunk
            const int kb = kk * 32 + qc * 4;      // byte offset of k pair
            uint32_t a[4][4], b[8][2];
#pragma unroll
            for (int mt = 0; mt < 4; ++mt) {
                int r = mbase + mt * 16 + qr;
                a[mt][0] = *(const uint32_t*)(base + SWZ((uint32_t)(r * 128 + kb)));
                a[mt][1] = *(const uint32_t*)(base + SWZ((uint32_t)((r + 8) * 128 + kb)));
                a[mt][2] = *(const uint32_t*)(base + SWZ((uint32_t)(r * 128 + kb + 16)));
                a[mt][3] = *(const uint32_t*)(base + SWZ((uint32_t)((r + 8) * 128 + kb + 16)));
            }
#pragma unroll
            for (int nt = 0; nt < 8; ++nt) {
                int n = nbase + nt * 8 + qr;
                b[nt][0] = *(const uint32_t*)(base + A_TILE_BYTES + SWZ((uint32_t)(n * 128 + kb)));
                b[nt][1] = *(const uint32_t*)(base + A_TILE_BYTES + SWZ((uint32_t)(n * 128 + kb + 16)));
            }
#pragma unroll
            for (int mt = 0; mt < 4; ++mt)
#pragma unroll
                for (int nt = 0; nt < 8; ++nt)
                    mma_f16(acc[mt][nt], a[mt], b[nt]);
        }

        cp_wait<STAGES - 2>();
        __syncthreads();
    }

    // ---- epilogue: regs -> GMEM with q/k/v region remap ----
    // out column n -> region r = n>>12, elem e = n&4095; region stride M*4096
    {
        const int rgn = n0 >> 12;
        float* obase = out + (size_t)rgn * ((size_t)M_TOTAL * 4096)
                           + (size_t)m0 * 4096 + (size_t)(n0 & 4095);
#pragma unroll
        for (int mt = 0; mt < 4; ++mt) {
            int m = mbase + mt * 16 + qr;
#pragma unroll
            for (int nt = 0; nt < 8; ++nt) {
                int ncol = nbase + nt * 8 + 2 * qc;
                *(float2*)(obase + (size_t)m * 4096 + ncol) =
                    make_float2(acc[mt][nt][0], acc[mt][nt][1]);
                *(float2*)(obase + (size_t)(m + 8) * 4096 + ncol) =
                    make_float2(acc[mt][nt][2], acc[mt][nt][3]);
            }
        }
    }
}

// ================= launch =================
extern "C" void kernel_launch(void* const* d_in, const int* in_sizes, int n_in,
                              void* d_out, int out_size) {
    const float* X = (const float*)d_in[0];   // hidden_states [4,4096,4096]
    const float* W = (const float*)d_in[1];   // qkv_proj [12288,4096]
    float* out = (float*)d_out;               // q|k|v, 3 x [16384,4096]
    (void)in_sizes; (void)n_in; (void)out_size;

    cudaFuncSetAttribute(qkv_gemm_kernel,
                         cudaFuncAttributeMaxDynamicSharedMemorySize, SMEM_BYTES);

    __half* Xh = nullptr;
    __half* Wh = nullptr;
    cudaGetSymbolAddress((void**)&Xh, g_Xh);
    cudaGetSymbolAddress((void**)&Wh, g_Wh);

    cvt_f16_kernel<<<1184, 256>>>(X, Xh, (M_TOTAL * (K_TOTAL / 4)));
    cvt_f16_kernel<<<1184, 256>>>(W, Wh, (N_TOTAL * (K_TOTAL / 4)));
    qkv_gemm_kernel<<<MT * NT, 256, SMEM_BYTES>>>(out);
}